// round 14
// baseline (speedup 1.0000x reference)
#include <cuda_runtime.h>
#include <cuda_device_runtime_api.h>

#define ROWS 4096
#define COLS 6144
#define THREADS 128
#define NWARPS (THREADS / 32)

#define FTHREADS 1024
#define FWARPS (FTHREADS / 32)

// Scratch partials (no allocation allowed in kernel_launch)
__device__ float g_r[1368];     // rows 0,3,...,4095 (1366 used, padded for float4)
__device__ float g_t[1368];     // rows 1,4,...,4093 (1365 used, padded)
__device__ float g_phi[ROWS];   // every row

// sigmoid(x) = 0.5*tanh(x/2) + 0.5 : one MUFU (TANH) instead of EX2+RCP.
__device__ __forceinline__ float sigmoidf(float x) {
    float y;
    asm("tanh.approx.f32 %0, %1;" : "=f"(y) : "f"(0.5f * x));
    return fmaf(0.5f, y, 0.5f);
}
__device__ __forceinline__ float circd(float ad) { return fminf(ad, 1.0f - ad); }

struct Tile12 { float a0,a1,a2,a3,b0,b1,b2,b3,c0,c1,c2,c3; };

__device__ __forceinline__ Tile12 tile_absdiff(float4 pa, float4 ta, float4 pb, float4 tb,
                                               float4 pc, float4 tc) {
    Tile12 v;
    v.a0 = fabsf(sigmoidf(pa.x) - ta.x);
    v.a1 = fabsf(sigmoidf(pa.y) - ta.y);
    v.a2 = fabsf(sigmoidf(pa.z) - ta.z);   // col 12k+2
    v.a3 = fabsf(sigmoidf(pa.w) - ta.w);
    v.b0 = fabsf(sigmoidf(pb.x) - tb.x);
    v.b1 = fabsf(sigmoidf(pb.y) - tb.y);   // col 12k+5
    v.b2 = fabsf(sigmoidf(pb.z) - tb.z);
    v.b3 = fabsf(sigmoidf(pb.w) - tb.w);
    v.c0 = fabsf(sigmoidf(pc.x) - tc.x);   // col 12k+8
    v.c1 = fabsf(sigmoidf(pc.y) - tc.y);
    v.c2 = fabsf(sigmoidf(pc.z) - tc.z);
    v.c3 = fabsf(sigmoidf(pc.w) - tc.w);   // col 12k+11
    return v;
}
__device__ __forceinline__ float tile_sum(const Tile12& v) {
    return ((v.a0 + v.a1) + (v.a2 + v.a3)) + ((v.b0 + v.b1) + (v.b2 + v.b3))
         + ((v.c0 + v.c1) + (v.c2 + v.c3));
}
// phi contribution for tile index k (valid phi cols < 4096): full if k<341,
// only a2 (col 4094) if k==341, none if k>341.
__device__ __forceinline__ float tile_phi(const Tile12& v, unsigned int k) {
    if (k > 341u) return 0.0f;
    float ph = circd(v.a2);
    if (k < 341u) ph += circd(v.b1) + circd(v.c0) + circd(v.c3);
    return ph;
}

__global__ void __launch_bounds__(THREADS)
spherical_pass1(const float* __restrict__ preds, const float* __restrict__ targs) {
    const int r = blockIdx.x;
    const int rowmod = r % 3;
    const bool wantRT = (rowmod < 2);
    const float4* __restrict__ p4 = (const float4*)(preds + (size_t)r * COLS);
    const float4* __restrict__ t4 = (const float4*)(targs + (size_t)r * COLS);

    float srt = 0.0f, sphi = 0.0f;

    // 4 tiles per thread: k, k+128, k+256, k+384 — processed as 2 pairs,
    // each pair front-batches 12 LDG.128.
#pragma unroll
    for (int half = 0; half < 2; half++) {
        const unsigned int ka = threadIdx.x + (unsigned int)(half * 2 * THREADS);
        const unsigned int kb = ka + THREADS;
        // Short rows (phi-only): tiles > 341 are dead weight.
        const bool la = wantRT || (ka <= 341u);
        const bool lb = wantRT || (kb <= 341u);
        const int ia = 3 * (int)ka, ib = 3 * (int)kb;

        float4 z = make_float4(0.f, 0.f, 0.f, 0.f);
        float4 pa1 = z, ta1 = z, pb1 = z, tb1 = z, pc1 = z, tc1 = z;
        float4 pa2 = z, ta2 = z, pb2 = z, tb2 = z, pc2 = z, tc2 = z;
        if (la) {
            pa1 = __ldcs(&p4[ia]);     ta1 = __ldcs(&t4[ia]);
            pb1 = __ldcs(&p4[ia + 1]); tb1 = __ldcs(&t4[ia + 1]);
            pc1 = __ldcs(&p4[ia + 2]); tc1 = __ldcs(&t4[ia + 2]);
        }
        if (lb) {
            pa2 = __ldcs(&p4[ib]);     ta2 = __ldcs(&t4[ib]);
            pb2 = __ldcs(&p4[ib + 1]); tb2 = __ldcs(&t4[ib + 1]);
            pc2 = __ldcs(&p4[ib + 2]); tc2 = __ldcs(&t4[ib + 2]);
        }

        if (la) {
            Tile12 v = tile_absdiff(pa1, ta1, pb1, tb1, pc1, tc1);
            if (wantRT) srt += tile_sum(v);
            sphi += tile_phi(v, ka);
        }
        if (lb) {
            Tile12 v = tile_absdiff(pa2, ta2, pb2, tb2, pc2, tc2);
            if (wantRT) srt += tile_sum(v);
            sphi += tile_phi(v, kb);
        }
    }

    cudaTriggerProgrammaticLaunchCompletion();

    // Deterministic block reduction
    __shared__ float shA[NWARPS], shB[NWARPS];
#pragma unroll
    for (int o = 16; o > 0; o >>= 1) {
        srt  += __shfl_down_sync(0xFFFFFFFFu, srt,  o);
        sphi += __shfl_down_sync(0xFFFFFFFFu, sphi, o);
    }
    const int lane = threadIdx.x & 31;
    const int warp = threadIdx.x >> 5;
    if (lane == 0) { shA[warp] = srt; shB[warp] = sphi; }
    __syncthreads();

    if (threadIdx.x == 0) {
        float a = shA[0], b = shB[0];
#pragma unroll
        for (int w = 1; w < NWARPS; w++) { a += shA[w]; b += shB[w]; }
        if (rowmod == 0)      g_r[r / 3] = a;
        else if (rowmod == 1) g_t[r / 3] = a;
        g_phi[r] = b;
    }
}

__global__ void __launch_bounds__(FTHREADS)
spherical_pass2(float* __restrict__ out) {
    cudaGridDependencySynchronize();

    float rs = 0.0f, ts = 0.0f, ps = 0.0f;
    const float4* r4   = (const float4*)g_r;      // 342 float4 (pad slots never written: stay 0)
    const float4* t4   = (const float4*)g_t;
    const float4* phi4 = (const float4*)g_phi;    // 1024 float4

    if (threadIdx.x < 342) {
        float4 v = __ldcg(&r4[threadIdx.x]);
        rs = (v.x + v.y) + (v.z + v.w);
        float4 w = __ldcg(&t4[threadIdx.x]);
        ts = (w.x + w.y) + (w.z + w.w);
    }
    {
        float4 v = __ldcg(&phi4[threadIdx.x]);
        ps = (v.x + v.y) + (v.z + v.w);
    }

    __shared__ float sh[3][FWARPS];
#pragma unroll
    for (int o = 16; o > 0; o >>= 1) {
        rs += __shfl_down_sync(0xFFFFFFFFu, rs, o);
        ts += __shfl_down_sync(0xFFFFFFFFu, ts, o);
        ps += __shfl_down_sync(0xFFFFFFFFu, ps, o);
    }
    const int lane = threadIdx.x & 31;
    const int warp = threadIdx.x >> 5;
    if (lane == 0) { sh[0][warp] = rs; sh[1][warp] = ts; sh[2][warp] = ps; }
    __syncthreads();
    if (warp == 0) {
        rs = (lane < FWARPS) ? sh[0][lane] : 0.0f;
        ts = (lane < FWARPS) ? sh[1][lane] : 0.0f;
        ps = (lane < FWARPS) ? sh[2][lane] : 0.0f;
#pragma unroll
        for (int o = 16; o > 0; o >>= 1) {
            rs += __shfl_down_sync(0xFFFFFFFFu, rs, o);
            ts += __shfl_down_sync(0xFFFFFFFFu, ts, o);
            ps += __shfl_down_sync(0xFFFFFFFFu, ps, o);
        }
        if (lane == 0) {
            float r_loss   = rs / (1366.0f * 6144.0f);
            float t_loss   = ts / (1365.0f * 6144.0f);
            float phi_loss = ps / (4096.0f * 2048.0f);
            out[0] = r_loss + t_loss + phi_loss;
            out[1] = r_loss;
            out[2] = t_loss;
            out[3] = phi_loss;
        }
    }
}

extern "C" void kernel_launch(void* const* d_in, const int* in_sizes, int n_in,
                              void* d_out, int out_size) {
    const float* preds = (const float*)d_in[0];
    const float* targs = (const float*)d_in[1];
    float* out = (float*)d_out;
    (void)in_sizes; (void)n_in; (void)out_size;

    spherical_pass1<<<ROWS, THREADS>>>(preds, targs);

    cudaLaunchAttribute attrs[1];
    attrs[0].id = cudaLaunchAttributeProgrammaticStreamSerialization;
    attrs[0].val.programmaticStreamSerializationAllowed = 1;

    cudaLaunchConfig_t cfg = {};
    cfg.gridDim = dim3(1, 1, 1);
    cfg.blockDim = dim3(FTHREADS, 1, 1);
    cfg.dynamicSmemBytes = 0;
    cfg.stream = 0;
    cfg.attrs = attrs;
    cfg.numAttrs = 1;

    cudaLaunchKernelEx(&cfg, spherical_pass2, out);
}

// round 15
// speedup vs baseline: 1.0088x; 1.0088x over previous
#include <cuda_runtime.h>
#include <cuda_device_runtime_api.h>

#define ROWS 4096
#define COLS 6144
#define THREADS 256
#define NWARPS (THREADS / 32)

#define FTHREADS 1024
#define FWARPS (FTHREADS / 32)

// Scratch partials (no allocation allowed in kernel_launch)
__device__ float g_r[1368];     // rows 0,3,...,4095 (1366 used, padded for float4)
__device__ float g_t[1368];     // rows 1,4,...,4093 (1365 used, padded)
__device__ float g_phi[ROWS];   // every row

// sigmoid(x) = 0.5*tanh(x/2) + 0.5 : one MUFU (TANH) instead of EX2+RCP.
__device__ __forceinline__ float sigmoidf(float x) {
    float y;
    asm("tanh.approx.f32 %0, %1;" : "=f"(y) : "f"(0.5f * x));
    return fmaf(0.5f, y, 0.5f);
}
__device__ __forceinline__ float circd(float ad) { return fminf(ad, 1.0f - ad); }

// Per-12-col tile: abs-diffs for all 12 elements.
struct Tile12 { float a0,a1,a2,a3,b0,b1,b2,b3,c0,c1,c2,c3; };

__device__ __forceinline__ Tile12 tile_absdiff(float4 pa, float4 ta, float4 pb, float4 tb,
                                               float4 pc, float4 tc) {
    Tile12 v;
    v.a0 = fabsf(sigmoidf(pa.x) - ta.x);
    v.a1 = fabsf(sigmoidf(pa.y) - ta.y);
    v.a2 = fabsf(sigmoidf(pa.z) - ta.z);   // col 12k+2
    v.a3 = fabsf(sigmoidf(pa.w) - ta.w);
    v.b0 = fabsf(sigmoidf(pb.x) - tb.x);
    v.b1 = fabsf(sigmoidf(pb.y) - tb.y);   // col 12k+5
    v.b2 = fabsf(sigmoidf(pb.z) - tb.z);
    v.b3 = fabsf(sigmoidf(pb.w) - tb.w);
    v.c0 = fabsf(sigmoidf(pc.x) - tc.x);   // col 12k+8
    v.c1 = fabsf(sigmoidf(pc.y) - tc.y);
    v.c2 = fabsf(sigmoidf(pc.z) - tc.z);
    v.c3 = fabsf(sigmoidf(pc.w) - tc.w);   // col 12k+11
    return v;
}
__device__ __forceinline__ float tile_sum(const Tile12& v) {
    return ((v.a0 + v.a1) + (v.a2 + v.a3)) + ((v.b0 + v.b1) + (v.b2 + v.b3))
         + ((v.c0 + v.c1) + (v.c2 + v.c3));
}

__global__ void __launch_bounds__(THREADS)
spherical_pass1(const float* __restrict__ preds, const float* __restrict__ targs) {
    const int r = blockIdx.x;
    const int rowmod = r % 3;
    const bool wantRT = (rowmod < 2);
    const float4* __restrict__ p4 = (const float4*)(preds + (size_t)r * COLS);
    const float4* __restrict__ t4 = (const float4*)(targs + (size_t)r * COLS);

    const unsigned int k1 = threadIdx.x;            // 0..255  : phi-full tile always
    const unsigned int k2 = threadIdx.x + THREADS;  // 256..511: phi iff k2<=341 / <341
    const int i1 = 3 * (int)k1;
    const int i2 = 3 * (int)k2;

    // Tile 2 participation: long rows always; short rows only k2 <= 341.
    const bool t2_load = wantRT || (k2 <= 341u);

    // ---- front-batch ALL loads ----
    float4 pa1 = __ldcs(&p4[i1]),     ta1 = __ldcs(&t4[i1]);
    float4 pb1 = __ldcs(&p4[i1 + 1]), tb1 = __ldcs(&t4[i1 + 1]);
    float4 pc1 = __ldcs(&p4[i1 + 2]), tc1 = __ldcs(&t4[i1 + 2]);
    float4 z = make_float4(0.f, 0.f, 0.f, 0.f);
    float4 pa2 = z, ta2 = z, pb2 = z, tb2 = z, pc2 = z, tc2 = z;
    if (t2_load) {
        pa2 = __ldcs(&p4[i2]);     ta2 = __ldcs(&t4[i2]);
        pb2 = __ldcs(&p4[i2 + 1]); tb2 = __ldcs(&t4[i2 + 1]);
        pc2 = __ldcs(&p4[i2 + 2]); tc2 = __ldcs(&t4[i2 + 2]);
    }

    float srt = 0.0f, sphi = 0.0f;

    // ---- tile 1: k1 < 256 -> always fully below phi boundary ----
    {
        Tile12 v = tile_absdiff(pa1, ta1, pb1, tb1, pc1, tc1);
        if (wantRT) srt += tile_sum(v);
        sphi += circd(v.a2) + circd(v.b1) + circd(v.c0) + circd(v.c3);
    }

    // ---- tile 2 ----
    if (t2_load) {
        Tile12 v = tile_absdiff(pa2, ta2, pb2, tb2, pc2, tc2);
        if (wantRT) srt += tile_sum(v);
        if (k2 <= 341u) {
            float ph = circd(v.a2);                       // col 12k+2 (4094 at k2=341)
            if (k2 < 341u) ph += circd(v.b1) + circd(v.c0) + circd(v.c3);
            sphi += ph;
        }
    }

    cudaTriggerProgrammaticLaunchCompletion();

    // Deterministic block reduction
    __shared__ float shA[NWARPS], shB[NWARPS];
#pragma unroll
    for (int o = 16; o > 0; o >>= 1) {
        srt  += __shfl_down_sync(0xFFFFFFFFu, srt,  o);
        sphi += __shfl_down_sync(0xFFFFFFFFu, sphi, o);
    }
    const int lane = threadIdx.x & 31;
    const int warp = threadIdx.x >> 5;
    if (lane == 0) { shA[warp] = srt; shB[warp] = sphi; }
    __syncthreads();

    if (threadIdx.x == 0) {
        float a = shA[0], b = shB[0];
#pragma unroll
        for (int w = 1; w < NWARPS; w++) { a += shA[w]; b += shB[w]; }
        if (rowmod == 0)      g_r[r / 3] = a;
        else if (rowmod == 1) g_t[r / 3] = a;
        g_phi[r] = b;
    }
}

__global__ void __launch_bounds__(FTHREADS)
spherical_pass2(float* __restrict__ out) {
    cudaGridDependencySynchronize();

    float rs = 0.0f, ts = 0.0f, ps = 0.0f;
    const float4* r4   = (const float4*)g_r;      // 342 float4 (pad slots never written: stay 0)
    const float4* t4   = (const float4*)g_t;
    const float4* phi4 = (const float4*)g_phi;    // 1024 float4

    if (threadIdx.x < 342) {
        float4 v = __ldcg(&r4[threadIdx.x]);
        rs = (v.x + v.y) + (v.z + v.w);
        float4 w = __ldcg(&t4[threadIdx.x]);
        ts = (w.x + w.y) + (w.z + w.w);
    }
    {
        float4 v = __ldcg(&phi4[threadIdx.x]);
        ps = (v.x + v.y) + (v.z + v.w);
    }

    __shared__ float sh[3][FWARPS];
#pragma unroll
    for (int o = 16; o > 0; o >>= 1) {
        rs += __shfl_down_sync(0xFFFFFFFFu, rs, o);
        ts += __shfl_down_sync(0xFFFFFFFFu, ts, o);
        ps += __shfl_down_sync(0xFFFFFFFFu, ps, o);
    }
    const int lane = threadIdx.x & 31;
    const int warp = threadIdx.x >> 5;
    if (lane == 0) { sh[0][warp] = rs; sh[1][warp] = ts; sh[2][warp] = ps; }
    __syncthreads();
    if (warp == 0) {
        rs = (lane < FWARPS) ? sh[0][lane] : 0.0f;
        ts = (lane < FWARPS) ? sh[1][lane] : 0.0f;
        ps = (lane < FWARPS) ? sh[2][lane] : 0.0f;
#pragma unroll
        for (int o = 16; o > 0; o >>= 1) {
            rs += __shfl_down_sync(0xFFFFFFFFu, rs, o);
            ts += __shfl_down_sync(0xFFFFFFFFu, ts, o);
            ps += __shfl_down_sync(0xFFFFFFFFu, ps, o);
        }
        if (lane == 0) {
            float r_loss   = rs / (1366.0f * 6144.0f);
            float t_loss   = ts / (1365.0f * 6144.0f);
            float phi_loss = ps / (4096.0f * 2048.0f);
            out[0] = r_loss + t_loss + phi_loss;
            out[1] = r_loss;
            out[2] = t_loss;
            out[3] = phi_loss;
        }
    }
}

extern "C" void kernel_launch(void* const* d_in, const int* in_sizes, int n_in,
                              void* d_out, int out_size) {
    const float* preds = (const float*)d_in[0];
    const float* targs = (const float*)d_in[1];
    float* out = (float*)d_out;
    (void)in_sizes; (void)n_in; (void)out_size;

    spherical_pass1<<<ROWS, THREADS>>>(preds, targs);

    cudaLaunchAttribute attrs[1];
    attrs[0].id = cudaLaunchAttributeProgrammaticStreamSerialization;
    attrs[0].val.programmaticStreamSerializationAllowed = 1;

    cudaLaunchConfig_t cfg = {};
    cfg.gridDim = dim3(1, 1, 1);
    cfg.blockDim = dim3(FTHREADS, 1, 1);
    cfg.dynamicSmemBytes = 0;
    cfg.stream = 0;
    cfg.attrs = attrs;
    cfg.numAttrs = 1;

    cudaLaunchKernelEx(&cfg, spherical_pass2, out);
}